// round 11
// baseline (speedup 1.0000x reference)
#include <cuda_runtime.h>
#include <cuda_fp16.h>
#include <cuda_bf16.h>
#include <cstdint>

#define N_NODES 100000
#define N_EDGES 1600000
#define IN_F    64
#define N_CLS   64

// Scratch: g = feat @ W^T in fp16 (12.8 MB -> L2-resident), CSR offsets
__device__ __half g_buf[(size_t)N_NODES * N_CLS];
__device__ int    g_row_start[N_NODES + 1];

#define NB_ROW  ((N_EDGES / 4 + 255) / 256)   /* rowptr blocks */
#define NB_GEMM ((N_NODES + 63) / 64)         /* gemm blocks   */

// Edge-balanced SpMM: each warp owns ~EPW edges' worth of whole rows.
#define EPW      128
#define N_WARPS  (N_EDGES / EPW)              /* 12500 */

// ---------------------------------------------------------------------------
// tf32 mma helpers
// ---------------------------------------------------------------------------
__device__ __forceinline__ unsigned f2tf32(float x) {
    unsigned u;
    asm("cvt.rna.tf32.f32 %0, %1;" : "=r"(u) : "f"(x));
    return u;
}
__device__ __forceinline__ void mma_tf32(float& c0, float& c1, float& c2, float& c3,
                                         unsigned a0, unsigned a1, unsigned a2, unsigned a3,
                                         unsigned b0, unsigned b1) {
    asm("mma.sync.aligned.m16n8k8.row.col.f32.tf32.tf32.f32 "
        "{%0,%1,%2,%3}, {%4,%5,%6,%7}, {%8,%9}, {%0,%1,%2,%3};"
        : "+f"(c0), "+f"(c1), "+f"(c2), "+f"(c3)
        : "r"(a0), "r"(a1), "r"(a2), "r"(a3), "r"(b0), "r"(b1));
}

// ---------------------------------------------------------------------------
// Fused prep kernel: blocks [0, NB_ROW) build row_start (transition scan),
// blocks [NB_ROW, NB_ROW+NB_GEMM) compute g = half(feat @ W^T) via tf32 mma.
// ---------------------------------------------------------------------------
#define SM_PAD 68
__global__ __launch_bounds__(256) void prep_kernel(const int* __restrict__ edge_row,
                                                   int* __restrict__ row_start,
                                                   const float* __restrict__ feat,
                                                   const float* __restrict__ W,
                                                   __half* __restrict__ g) {
    __shared__ float sA[64 * SM_PAD];
    __shared__ float sB[64 * SM_PAD];

    if (blockIdx.x < NB_ROW) {
        int t = blockIdx.x * blockDim.x + threadIdx.x;
        if (t >= N_EDGES / 4) return;
        int4 r4 = ((const int4*)edge_row)[t];
        int e0 = t * 4;
        int prev = (t == 0) ? -1 : __ldg(&edge_row[e0 - 1]);

        for (int q = prev + 1; q <= r4.x; ++q) row_start[q] = e0;
        for (int q = r4.x + 1; q <= r4.y; ++q) row_start[q] = e0 + 1;
        for (int q = r4.y + 1; q <= r4.z; ++q) row_start[q] = e0 + 2;
        for (int q = r4.z + 1; q <= r4.w; ++q) row_start[q] = e0 + 3;

        if (e0 + 4 == N_EDGES)
            for (int q = r4.w + 1; q <= N_NODES; ++q) row_start[q] = N_EDGES;
        return;
    }

    // ---- GEMM tile 64x64, 8 warps (4x2) ----
    int tid  = threadIdx.x;
    int lane = tid & 31;
    int warp = tid >> 5;
    int row0 = (blockIdx.x - NB_ROW) * 64;
    int maxrow = N_NODES - row0;

    for (int idx = tid; idx < 64 * 16; idx += 256) {
        int n = idx >> 4, q = idx & 15;
        float4 v = ((const float4*)W)[idx];
        float* dst = &sB[n * SM_PAD + q * 4];
        dst[0] = v.x; dst[1] = v.y; dst[2] = v.z; dst[3] = v.w;
    }
    for (int idx = tid; idx < 64 * 16; idx += 256) {
        int r = idx >> 4, q = idx & 15;
        float4 v = (r < maxrow) ? __ldcs(&((const float4*)(feat + (size_t)row0 * 64))[idx])
                                : make_float4(0.f, 0.f, 0.f, 0.f);
        float* dst = &sA[r * SM_PAD + q * 4];
        dst[0] = v.x; dst[1] = v.y; dst[2] = v.z; dst[3] = v.w;
    }
    __syncthreads();

    int g4 = lane >> 2;
    int t4 = lane & 3;
    int warp_m = warp >> 1;
    int warp_n = warp & 1;

    float acc[4][4];
    #pragma unroll
    for (int i = 0; i < 4; ++i)
        #pragma unroll
        for (int j = 0; j < 4; ++j) acc[i][j] = 0.f;

    int ra = warp_m * 16 + g4;

    #pragma unroll
    for (int ks = 0; ks < 8; ++ks) {
        int k0 = ks * 8;
        unsigned a0 = f2tf32(sA[ra * SM_PAD + k0 + t4]);
        unsigned a1 = f2tf32(sA[(ra + 8) * SM_PAD + k0 + t4]);
        unsigned a2 = f2tf32(sA[ra * SM_PAD + k0 + t4 + 4]);
        unsigned a3 = f2tf32(sA[(ra + 8) * SM_PAD + k0 + t4 + 4]);
        #pragma unroll
        for (int nt = 0; nt < 4; ++nt) {
            int n = (warp_n * 4 + nt) * 8 + g4;
            unsigned b0 = f2tf32(sB[n * SM_PAD + k0 + t4]);
            unsigned b1 = f2tf32(sB[n * SM_PAD + k0 + t4 + 4]);
            mma_tf32(acc[nt][0], acc[nt][1], acc[nt][2], acc[nt][3],
                     a0, a1, a2, a3, b0, b1);
        }
    }

    #pragma unroll
    for (int nt = 0; nt < 4; ++nt) {
        int col = (warp_n * 4 + nt) * 8 + 2 * t4;
        if (ra < maxrow) {
            __half2 h = __floats2half2_rn(acc[nt][0], acc[nt][1]);
            *(__half2*)(g + (size_t)(row0 + ra) * 64 + col) = h;
        }
        if (ra + 8 < maxrow) {
            __half2 h = __floats2half2_rn(acc[nt][2], acc[nt][3]);
            *(__half2*)(g + (size_t)(row0 + ra + 8) * 64 + col) = h;
        }
    }
}

// ---------------------------------------------------------------------------
// SpMM, edge-balanced: warp w owns whole rows
//   [ edge_row[w*EPW-1]+1 , edge_row[(w+1)*EPW-1]+1 )        (no search!)
// since row_start[r] >= K  <=>  r > edge_row[K-1]  for sorted edge_row.
// Every warp processes ~EPW edges regardless of degree distribution.
// Within a row: 16 lanes per edge, lane = half*16+sub, uint2 (4 fp16 feats).
// ---------------------------------------------------------------------------
__global__ __launch_bounds__(256) void spmm_kernel(const int* __restrict__ edge_row,
                                                   const int* __restrict__ row_start,
                                                   const int* __restrict__ edge_col,
                                                   const float* __restrict__ edge_val,
                                                   const __half* __restrict__ g,
                                                   const float* __restrict__ b,
                                                   float* __restrict__ out) {
    int w = (blockIdx.x * blockDim.x + threadIdx.x) >> 5;
    int lane = threadIdx.x & 31;
    if (w >= N_WARPS) return;

    int half = lane >> 4;
    int sub  = lane & 15;

    int nlo = (w == 0) ? 0 : __ldg(&edge_row[w * EPW - 1]) + 1;
    int nhi = (w == N_WARPS - 1) ? N_NODES : __ldg(&edge_row[(w + 1) * EPW - 1]) + 1;
    if (nlo >= nhi) return;

    const uint2* gp = (const uint2*)g;            // row = 16 uint2 (128 B)
    float4 bv = ((const float4*)b)[sub];          // bias feats sub*4..sub*4+3

    int s = __ldg(&row_start[nlo]);

    for (int r = nlo; r < nhi; ++r) {
        int e = __ldg(&row_start[r + 1]);
        float4 acc = make_float4(0.f, 0.f, 0.f, 0.f);

        for (int base = s; base < e; base += 32) {
            int cnt = min(32, e - base);
            int   c_l = 0;
            float v_l = 0.f;
            if (lane < cnt) {
                c_l = __ldcs(&edge_col[base + lane]);
                v_l = __ldcs(&edge_val[base + lane]);
            }

            int j = 0;
            for (; j + 8 <= cnt; j += 8) {
                int m0 = j + half, m1 = j + 2 + half, m2 = j + 4 + half, m3 = j + 6 + half;
                int c0 = __shfl_sync(0xffffffffu, c_l, m0);
                int c1 = __shfl_sync(0xffffffffu, c_l, m1);
                int c2 = __shfl_sync(0xffffffffu, c_l, m2);
                int c3 = __shfl_sync(0xffffffffu, c_l, m3);
                float v0 = __shfl_sync(0xffffffffu, v_l, m0);
                float v1 = __shfl_sync(0xffffffffu, v_l, m1);
                float v2 = __shfl_sync(0xffffffffu, v_l, m2);
                float v3 = __shfl_sync(0xffffffffu, v_l, m3);
                uint2 a0 = gp[(size_t)c0 * 16 + sub];
                uint2 a1 = gp[(size_t)c1 * 16 + sub];
                uint2 a2 = gp[(size_t)c2 * 16 + sub];
                uint2 a3 = gp[(size_t)c3 * 16 + sub];
                {
                    float2 lo = __half22float2(*(const __half2*)&a0.x);
                    float2 hi = __half22float2(*(const __half2*)&a0.y);
                    acc.x = fmaf(v0, lo.x, acc.x); acc.y = fmaf(v0, lo.y, acc.y);
                    acc.z = fmaf(v0, hi.x, acc.z); acc.w = fmaf(v0, hi.y, acc.w);
                }
                {
                    float2 lo = __half22float2(*(const __half2*)&a1.x);
                    float2 hi = __half22float2(*(const __half2*)&a1.y);
                    acc.x = fmaf(v1, lo.x, acc.x); acc.y = fmaf(v1, lo.y, acc.y);
                    acc.z = fmaf(v1, hi.x, acc.z); acc.w = fmaf(v1, hi.y, acc.w);
                }
                {
                    float2 lo = __half22float2(*(const __half2*)&a2.x);
                    float2 hi = __half22float2(*(const __half2*)&a2.y);
                    acc.x = fmaf(v2, lo.x, acc.x); acc.y = fmaf(v2, lo.y, acc.y);
                    acc.z = fmaf(v2, hi.x, acc.z); acc.w = fmaf(v2, hi.y, acc.w);
                }
                {
                    float2 lo = __half22float2(*(const __half2*)&a3.x);
                    float2 hi = __half22float2(*(const __half2*)&a3.y);
                    acc.x = fmaf(v3, lo.x, acc.x); acc.y = fmaf(v3, lo.y, acc.y);
                    acc.z = fmaf(v3, hi.x, acc.z); acc.w = fmaf(v3, hi.y, acc.w);
                }
            }
            for (; j < cnt; j += 2) {
                int m = j + half;
                int   c = __shfl_sync(0xffffffffu, c_l, m & 31);
                float v = __shfl_sync(0xffffffffu, v_l, m & 31);
                if (m < cnt) {
                    uint2 a = gp[(size_t)c * 16 + sub];
                    float2 lo = __half22float2(*(const __half2*)&a.x);
                    float2 hi = __half22float2(*(const __half2*)&a.y);
                    acc.x = fmaf(v, lo.x, acc.x); acc.y = fmaf(v, lo.y, acc.y);
                    acc.z = fmaf(v, hi.x, acc.z); acc.w = fmaf(v, hi.y, acc.w);
                }
            }
        }

        // combine halves, add bias, write row
        acc.x += __shfl_xor_sync(0xffffffffu, acc.x, 16);
        acc.y += __shfl_xor_sync(0xffffffffu, acc.y, 16);
        acc.z += __shfl_xor_sync(0xffffffffu, acc.z, 16);
        acc.w += __shfl_xor_sync(0xffffffffu, acc.w, 16);

        if (half == 0) {
            float4 o = make_float4(acc.x + bv.x, acc.y + bv.y,
                                   acc.z + bv.z, acc.w + bv.w);
            __stcs(&((float4*)(out + (size_t)r * 64))[sub], o);
        }
        s = e;
    }
}

// ---------------------------------------------------------------------------
extern "C" void kernel_launch(void* const* d_in, const int* in_sizes, int n_in,
                              void* d_out, int out_size) {
    const float* feat     = (const float*)d_in[0];
    const int*   edge_row = (const int*)  d_in[1];
    const int*   edge_col = (const int*)  d_in[2];
    const float* edge_val = (const float*)d_in[3];
    const float* W        = (const float*)d_in[4];
    const float* b        = (const float*)d_in[5];
    float*       out      = (float*)d_out;

    __half* g;
    int*    row_start;
    cudaGetSymbolAddress((void**)&g, g_buf);
    cudaGetSymbolAddress((void**)&row_start, g_row_start);

    // 1) fused: rowptr scan + g = half(feat @ W^T)
    prep_kernel<<<NB_ROW + NB_GEMM, 256>>>(edge_row, row_start, feat, W, g);

    // 2) out = A @ g + b   (edge-balanced warps, whole rows, no atomics)
    int total_threads = N_WARPS * 32;
    spmm_kernel<<<(total_threads + 255) / 256, 256>>>(edge_row, row_start, edge_col,
                                                      edge_val, g, b, out);
}

// round 12
// speedup vs baseline: 1.4480x; 1.4480x over previous
#include <cuda_runtime.h>
#include <cuda_fp16.h>
#include <cuda_bf16.h>
#include <cstdint>

#define N_NODES 100000
#define N_EDGES 1600000
#define IN_F    64
#define N_CLS   64

// Scratch: g = feat @ W^T in fp16 (12.8 MB -> L2-resident), CSR offsets
__device__ __half g_buf[(size_t)N_NODES * N_CLS];
__device__ int    g_row_start[N_NODES + 1];

#define NB_ROW  ((N_EDGES / 4 + 255) / 256)   /* rowptr blocks */
#define NB_GEMM ((N_NODES + 63) / 64)         /* gemm blocks   */

// ---------------------------------------------------------------------------
// tf32 mma helpers
// ---------------------------------------------------------------------------
__device__ __forceinline__ unsigned f2tf32(float x) {
    unsigned u;
    asm("cvt.rna.tf32.f32 %0, %1;" : "=r"(u) : "f"(x));
    return u;
}
__device__ __forceinline__ void mma_tf32(float& c0, float& c1, float& c2, float& c3,
                                         unsigned a0, unsigned a1, unsigned a2, unsigned a3,
                                         unsigned b0, unsigned b1) {
    asm("mma.sync.aligned.m16n8k8.row.col.f32.tf32.tf32.f32 "
        "{%0,%1,%2,%3}, {%4,%5,%6,%7}, {%8,%9}, {%0,%1,%2,%3};"
        : "+f"(c0), "+f"(c1), "+f"(c2), "+f"(c3)
        : "r"(a0), "r"(a1), "r"(a2), "r"(a3), "r"(b0), "r"(b1));
}

// ---------------------------------------------------------------------------
// Fused prep kernel: blocks [0, NB_ROW) build row_start (transition scan,
// prev row via shfl_up; only lane 0 touches gmem for the boundary),
// blocks [NB_ROW, ...) compute g = half(feat @ W^T) via tf32 mma.
// ---------------------------------------------------------------------------
#define SM_PAD 68
__global__ __launch_bounds__(256) void prep_kernel(const int* __restrict__ edge_row,
                                                   int* __restrict__ row_start,
                                                   const float* __restrict__ feat,
                                                   const float* __restrict__ W,
                                                   __half* __restrict__ g) {
    __shared__ float sA[64 * SM_PAD];
    __shared__ float sB[64 * SM_PAD];

    if (blockIdx.x < NB_ROW) {
        int t = blockIdx.x * blockDim.x + threadIdx.x;
        int lane = threadIdx.x & 31;
        if (t >= N_EDGES / 4) return;
        int4 r4 = ((const int4*)edge_row)[t];
        int e0 = t * 4;

        // previous row: shfl from lane-1's r4.w; lane 0 loads the boundary
        int prev_sh = __shfl_up_sync(0xffffffffu, r4.w, 1);
        int prev;
        if (lane == 0)
            prev = (t == 0) ? -1 : __ldg(&edge_row[e0 - 1]);
        else
            prev = prev_sh;

        for (int q = prev + 1; q <= r4.x; ++q) row_start[q] = e0;
        for (int q = r4.x + 1; q <= r4.y; ++q) row_start[q] = e0 + 1;
        for (int q = r4.y + 1; q <= r4.z; ++q) row_start[q] = e0 + 2;
        for (int q = r4.z + 1; q <= r4.w; ++q) row_start[q] = e0 + 3;

        if (e0 + 4 == N_EDGES)
            for (int q = r4.w + 1; q <= N_NODES; ++q) row_start[q] = N_EDGES;
        return;
    }

    // ---- GEMM tile 64x64, 8 warps (4x2) ----
    int tid  = threadIdx.x;
    int lane = tid & 31;
    int warp = tid >> 5;
    int row0 = (blockIdx.x - NB_ROW) * 64;
    int maxrow = N_NODES - row0;

    for (int idx = tid; idx < 64 * 16; idx += 256) {
        int n = idx >> 4, q = idx & 15;
        float4 v = ((const float4*)W)[idx];
        float* dst = &sB[n * SM_PAD + q * 4];
        dst[0] = v.x; dst[1] = v.y; dst[2] = v.z; dst[3] = v.w;
    }
    for (int idx = tid; idx < 64 * 16; idx += 256) {
        int r = idx >> 4, q = idx & 15;
        float4 v = (r < maxrow) ? __ldcs(&((const float4*)(feat + (size_t)row0 * 64))[idx])
                                : make_float4(0.f, 0.f, 0.f, 0.f);
        float* dst = &sA[r * SM_PAD + q * 4];
        dst[0] = v.x; dst[1] = v.y; dst[2] = v.z; dst[3] = v.w;
    }
    __syncthreads();

    int g4 = lane >> 2;
    int t4 = lane & 3;
    int warp_m = warp >> 1;
    int warp_n = warp & 1;

    float acc[4][4];
    #pragma unroll
    for (int i = 0; i < 4; ++i)
        #pragma unroll
        for (int j = 0; j < 4; ++j) acc[i][j] = 0.f;

    int ra = warp_m * 16 + g4;

    #pragma unroll
    for (int ks = 0; ks < 8; ++ks) {
        int k0 = ks * 8;
        unsigned a0 = f2tf32(sA[ra * SM_PAD + k0 + t4]);
        unsigned a1 = f2tf32(sA[(ra + 8) * SM_PAD + k0 + t4]);
        unsigned a2 = f2tf32(sA[ra * SM_PAD + k0 + t4 + 4]);
        unsigned a3 = f2tf32(sA[(ra + 8) * SM_PAD + k0 + t4 + 4]);
        #pragma unroll
        for (int nt = 0; nt < 4; ++nt) {
            int n = (warp_n * 4 + nt) * 8 + g4;
            unsigned b0 = f2tf32(sB[n * SM_PAD + k0 + t4]);
            unsigned b1 = f2tf32(sB[n * SM_PAD + k0 + t4 + 4]);
            mma_tf32(acc[nt][0], acc[nt][1], acc[nt][2], acc[nt][3],
                     a0, a1, a2, a3, b0, b1);
        }
    }

    #pragma unroll
    for (int nt = 0; nt < 4; ++nt) {
        int col = (warp_n * 4 + nt) * 8 + 2 * t4;
        if (ra < maxrow) {
            __half2 h = __floats2half2_rn(acc[nt][0], acc[nt][1]);
            *(__half2*)(g + (size_t)(row0 + ra) * 64 + col) = h;
        }
        if (ra + 8 < maxrow) {
            __half2 h = __floats2half2_rn(acc[nt][2], acc[nt][3]);
            *(__half2*)(g + (size_t)(row0 + ra + 8) * 64 + col) = h;
        }
    }
}

// ---------------------------------------------------------------------------
// SpMM: ONE WARP PER NODE (max parallelism), 8 lanes per edge.
// lane = slot*8 + sub; slot in [0,4) -> 4 edges in flight per step,
// sub in [0,8) -> lane loads uint4 = 8 fp16 feats of its edge's g row.
// One LDG.128 per 4 edges (0.25 LDG/edge); edge col/val read per-slot
// (uniform in 8-lane group -> L1 broadcast), no shfl in the hot loop.
// Final: shfl_xor(8) + shfl_xor(16) reduction; lanes 0-7 write the row.
// ---------------------------------------------------------------------------
__global__ __launch_bounds__(256) void spmm_kernel(const int* __restrict__ row_start,
                                                   const int* __restrict__ edge_col,
                                                   const float* __restrict__ edge_val,
                                                   const __half* __restrict__ g,
                                                   const float* __restrict__ b,
                                                   float* __restrict__ out) {
    int w = (blockIdx.x * blockDim.x + threadIdx.x) >> 5;
    int lane = threadIdx.x & 31;
    if (w >= N_NODES) return;

    int slot = lane >> 3;   // which of 4 concurrent edges
    int sub  = lane & 7;    // which 8-feature chunk of the row

    int s = __ldg(&row_start[w]);
    int e = __ldg(&row_start[w + 1]);

    const uint4* gp = (const uint4*)g;   // g row = 8 uint4 (128 B)

    float acc[8];
    #pragma unroll
    for (int k = 0; k < 8; ++k) acc[k] = 0.f;

    int i = s;
    // main loop: 8 edges per iteration (2 groups of 4), MLP = 2 gathers + 4 scalars
    for (; i + 8 <= e; i += 8) {
        int   ca = __ldcs(&edge_col[i + slot]);
        int   cb = __ldcs(&edge_col[i + 4 + slot]);
        float va = __ldcs(&edge_val[i + slot]);
        float vb = __ldcs(&edge_val[i + 4 + slot]);
        uint4 A = __ldg(&gp[(size_t)ca * 8 + sub]);
        uint4 B = __ldg(&gp[(size_t)cb * 8 + sub]);
        {
            float2 p0 = __half22float2(*(const __half2*)&A.x);
            float2 p1 = __half22float2(*(const __half2*)&A.y);
            float2 p2 = __half22float2(*(const __half2*)&A.z);
            float2 p3 = __half22float2(*(const __half2*)&A.w);
            acc[0] = fmaf(va, p0.x, acc[0]); acc[1] = fmaf(va, p0.y, acc[1]);
            acc[2] = fmaf(va, p1.x, acc[2]); acc[3] = fmaf(va, p1.y, acc[3]);
            acc[4] = fmaf(va, p2.x, acc[4]); acc[5] = fmaf(va, p2.y, acc[5]);
            acc[6] = fmaf(va, p3.x, acc[6]); acc[7] = fmaf(va, p3.y, acc[7]);
        }
        {
            float2 p0 = __half22float2(*(const __half2*)&B.x);
            float2 p1 = __half22float2(*(const __half2*)&B.y);
            float2 p2 = __half22float2(*(const __half2*)&B.z);
            float2 p3 = __half22float2(*(const __half2*)&B.w);
            acc[0] = fmaf(vb, p0.x, acc[0]); acc[1] = fmaf(vb, p0.y, acc[1]);
            acc[2] = fmaf(vb, p1.x, acc[2]); acc[3] = fmaf(vb, p1.y, acc[3]);
            acc[4] = fmaf(vb, p2.x, acc[4]); acc[5] = fmaf(vb, p2.y, acc[5]);
            acc[6] = fmaf(vb, p3.x, acc[6]); acc[7] = fmaf(vb, p3.y, acc[7]);
        }
    }
    // tail: 4 edges per iteration, invalid slots contribute v=0
    for (; i < e; i += 4) {
        int  m = i + slot;
        bool p = (m < e);
        int  mm = p ? m : i;                 // clamped, always valid
        int   c = __ldcs(&edge_col[mm]);
        float v = p ? __ldcs(&edge_val[mm]) : 0.f;
        uint4 A = __ldg(&gp[(size_t)c * 8 + sub]);
        float2 p0 = __half22float2(*(const __half2*)&A.x);
        float2 p1 = __half22float2(*(const __half2*)&A.y);
        float2 p2 = __half22float2(*(const __half2*)&A.z);
        float2 p3 = __half22float2(*(const __half2*)&A.w);
        acc[0] = fmaf(v, p0.x, acc[0]); acc[1] = fmaf(v, p0.y, acc[1]);
        acc[2] = fmaf(v, p1.x, acc[2]); acc[3] = fmaf(v, p1.y, acc[3]);
        acc[4] = fmaf(v, p2.x, acc[4]); acc[5] = fmaf(v, p2.y, acc[5]);
        acc[6] = fmaf(v, p3.x, acc[6]); acc[7] = fmaf(v, p3.y, acc[7]);
    }

    // reduce the 4 slots (features partitioned identically by sub)
    #pragma unroll
    for (int k = 0; k < 8; ++k) {
        acc[k] += __shfl_xor_sync(0xffffffffu, acc[k], 8);
        acc[k] += __shfl_xor_sync(0xffffffffu, acc[k], 16);
    }

    if (lane < 8) {
        // lane owns feats [lane*8, lane*8+8)
        float4 b0 = ((const float4*)b)[lane * 2];
        float4 b1 = ((const float4*)b)[lane * 2 + 1];
        float4 o0 = make_float4(acc[0] + b0.x, acc[1] + b0.y,
                                acc[2] + b0.z, acc[3] + b0.w);
        float4 o1 = make_float4(acc[4] + b1.x, acc[5] + b1.y,
                                acc[6] + b1.z, acc[7] + b1.w);
        float4* op = (float4*)(out + (size_t)w * 64 + lane * 8);
        __stcs(&op[0], o0);
        __stcs(&op[1], o1);
    }
}

// ---------------------------------------------------------------------------
extern "C" void kernel_launch(void* const* d_in, const int* in_sizes, int n_in,
                              void* d_out, int out_size) {
    const float* feat     = (const float*)d_in[0];
    const int*   edge_row = (const int*)  d_in[1];
    const int*   edge_col = (const int*)  d_in[2];
    const float* edge_val = (const float*)d_in[3];
    const float* W        = (const float*)d_in[4];
    const float* b        = (const float*)d_in[5];
    float*       out      = (float*)d_out;

    __half* g;
    int*    row_start;
    cudaGetSymbolAddress((void**)&g, g_buf);
    cudaGetSymbolAddress((void**)&row_start, g_row_start);

    // 1) fused: rowptr scan + g = half(feat @ W^T)
    prep_kernel<<<NB_ROW + NB_GEMM, 256>>>(edge_row, row_start, feat, W, g);

    // 2) out = A @ g + b   (one warp per node, 8 lanes per edge)
    int total_threads = N_NODES * 32;
    spmm_kernel<<<(total_threads + 255) / 256, 256>>>(row_start, edge_col, edge_val,
                                                      g, b, out);
}

// round 13
// speedup vs baseline: 1.6400x; 1.1326x over previous
#include <cuda_runtime.h>
#include <cuda_fp16.h>
#include <cuda_bf16.h>
#include <cstdint>

#define N_NODES 100000
#define N_EDGES 1600000
#define IN_F    64
#define N_CLS   64

// Scratch: g = feat @ W^T in fp16 (12.8 MB -> L2-resident), CSR offsets
__device__ __half g_buf[(size_t)N_NODES * N_CLS];
__device__ int    g_row_start[N_NODES + 1];

#define NB_ROW  ((N_EDGES / 4 + 255) / 256)   /* rowptr blocks */
#define NB_GEMM ((N_NODES + 63) / 64)         /* gemm blocks   */

// ---------------------------------------------------------------------------
// packed f32x2 helpers (fma.rn.f32x2 is never emitted by ptxas from C++)
// ---------------------------------------------------------------------------
__device__ __forceinline__ unsigned long long fma2(unsigned long long a,
                                                   unsigned long long b,
                                                   unsigned long long c) {
    unsigned long long d;
    asm("fma.rn.f32x2 %0, %1, %2, %3;" : "=l"(d) : "l"(a), "l"(b), "l"(c));
    return d;
}
__device__ __forceinline__ unsigned long long packff(float x, float y) {
    unsigned long long d;
    asm("mov.b64 %0, {%1, %2};" : "=l"(d) : "f"(x), "f"(y));
    return d;
}
__device__ __forceinline__ void unpack2(unsigned long long v, float& lo, float& hi) {
    asm("mov.b64 {%0, %1}, %2;" : "=f"(lo), "=f"(hi) : "l"(v));
}
// half2 bits -> packed f32x2 (b64); ptxas pairs the cvt outputs, pack mov folds
__device__ __forceinline__ unsigned long long h2_to_f32x2(unsigned h2) {
    unsigned long long d;
    asm("{\n\t"
        ".reg .b16 l, h;\n\t"
        ".reg .f32 fl, fh;\n\t"
        "mov.b32 {l, h}, %1;\n\t"
        "cvt.f32.f16 fl, l;\n\t"
        "cvt.f32.f16 fh, h;\n\t"
        "mov.b64 %0, {fl, fh};\n\t"
        "}" : "=l"(d) : "r"(h2));
    return d;
}

// ---------------------------------------------------------------------------
// tf32 mma helpers
// ---------------------------------------------------------------------------
__device__ __forceinline__ unsigned f2tf32(float x) {
    unsigned u;
    asm("cvt.rna.tf32.f32 %0, %1;" : "=r"(u) : "f"(x));
    return u;
}
__device__ __forceinline__ void mma_tf32(float& c0, float& c1, float& c2, float& c3,
                                         unsigned a0, unsigned a1, unsigned a2, unsigned a3,
                                         unsigned b0, unsigned b1) {
    asm("mma.sync.aligned.m16n8k8.row.col.f32.tf32.tf32.f32 "
        "{%0,%1,%2,%3}, {%4,%5,%6,%7}, {%8,%9}, {%0,%1,%2,%3};"
        : "+f"(c0), "+f"(c1), "+f"(c2), "+f"(c3)
        : "r"(a0), "r"(a1), "r"(a2), "r"(a3), "r"(b0), "r"(b1));
}

// ---------------------------------------------------------------------------
// Fused prep kernel: blocks [0, NB_ROW) build row_start (transition scan),
// blocks [NB_ROW, ...) compute g = half(feat @ W^T) via tf32 mma.
// ---------------------------------------------------------------------------
#define SM_PAD 68
__global__ __launch_bounds__(256) void prep_kernel(const int* __restrict__ edge_row,
                                                   int* __restrict__ row_start,
                                                   const float* __restrict__ feat,
                                                   const float* __restrict__ W,
                                                   __half* __restrict__ g) {
    __shared__ float sA[64 * SM_PAD];
    __shared__ float sB[64 * SM_PAD];

    if (blockIdx.x < NB_ROW) {
        int t = blockIdx.x * blockDim.x + threadIdx.x;
        if (t >= N_EDGES / 4) return;
        int4 r4 = ((const int4*)edge_row)[t];
        int e0 = t * 4;
        int prev = (t == 0) ? -1 : __ldg(&edge_row[e0 - 1]);

        for (int q = prev + 1; q <= r4.x; ++q) row_start[q] = e0;
        for (int q = r4.x + 1; q <= r4.y; ++q) row_start[q] = e0 + 1;
        for (int q = r4.y + 1; q <= r4.z; ++q) row_start[q] = e0 + 2;
        for (int q = r4.z + 1; q <= r4.w; ++q) row_start[q] = e0 + 3;

        if (e0 + 4 == N_EDGES)
            for (int q = r4.w + 1; q <= N_NODES; ++q) row_start[q] = N_EDGES;
        return;
    }

    // ---- GEMM tile 64x64, 8 warps (4x2) ----
    int tid  = threadIdx.x;
    int lane = tid & 31;
    int warp = tid >> 5;
    int row0 = (blockIdx.x - NB_ROW) * 64;
    int maxrow = N_NODES - row0;

    for (int idx = tid; idx < 64 * 16; idx += 256) {
        int n = idx >> 4, q = idx & 15;
        float4 v = ((const float4*)W)[idx];
        float* dst = &sB[n * SM_PAD + q * 4];
        dst[0] = v.x; dst[1] = v.y; dst[2] = v.z; dst[3] = v.w;
    }
    for (int idx = tid; idx < 64 * 16; idx += 256) {
        int r = idx >> 4, q = idx & 15;
        float4 v = (r < maxrow) ? __ldcs(&((const float4*)(feat + (size_t)row0 * 64))[idx])
                                : make_float4(0.f, 0.f, 0.f, 0.f);
        float* dst = &sA[r * SM_PAD + q * 4];
        dst[0] = v.x; dst[1] = v.y; dst[2] = v.z; dst[3] = v.w;
    }
    __syncthreads();

    int g4 = lane >> 2;
    int t4 = lane & 3;
    int warp_m = warp >> 1;
    int warp_n = warp & 1;

    float acc[4][4];
    #pragma unroll
    for (int i = 0; i < 4; ++i)
        #pragma unroll
        for (int j = 0; j < 4; ++j) acc[i][j] = 0.f;

    int ra = warp_m * 16 + g4;

    #pragma unroll
    for (int ks = 0; ks < 8; ++ks) {
        int k0 = ks * 8;
        unsigned a0 = f2tf32(sA[ra * SM_PAD + k0 + t4]);
        unsigned a1 = f2tf32(sA[(ra + 8) * SM_PAD + k0 + t4]);
        unsigned a2 = f2tf32(sA[ra * SM_PAD + k0 + t4 + 4]);
        unsigned a3 = f2tf32(sA[(ra + 8) * SM_PAD + k0 + t4 + 4]);
        #pragma unroll
        for (int nt = 0; nt < 4; ++nt) {
            int n = (warp_n * 4 + nt) * 8 + g4;
            unsigned b0 = f2tf32(sB[n * SM_PAD + k0 + t4]);
            unsigned b1 = f2tf32(sB[n * SM_PAD + k0 + t4 + 4]);
            mma_tf32(acc[nt][0], acc[nt][1], acc[nt][2], acc[nt][3],
                     a0, a1, a2, a3, b0, b1);
        }
    }

    #pragma unroll
    for (int nt = 0; nt < 4; ++nt) {
        int col = (warp_n * 4 + nt) * 8 + 2 * t4;
        if (ra < maxrow) {
            __half2 h = __floats2half2_rn(acc[nt][0], acc[nt][1]);
            *(__half2*)(g + (size_t)(row0 + ra) * 64 + col) = h;
        }
        if (ra + 8 < maxrow) {
            __half2 h = __floats2half2_rn(acc[nt][2], acc[nt][3]);
            *(__half2*)(g + (size_t)(row0 + ra + 8) * 64 + col) = h;
        }
    }
}

// ---------------------------------------------------------------------------
// SpMM: one warp per node, 8 lanes per edge (slot=lane>>3, sub=lane&7).
// uint4 gather: one LDG.128 serves a whole 128B g row across 8 lanes
// (0.25 gather-LDG/edge). Edge (col,val) prefetched ONE ITERATION AHEAD so
// the scalar->gather dependent chain is overlapped. Math uses fma.rn.f32x2:
// one packed FMA per half2 (16 FMA2/iter instead of 32 FFMA).
// ---------------------------------------------------------------------------
__global__ __launch_bounds__(256) void spmm_kernel(const int* __restrict__ row_start,
                                                   const int* __restrict__ edge_col,
                                                   const float* __restrict__ edge_val,
                                                   const __half* __restrict__ g,
                                                   const float* __restrict__ b,
                                                   float* __restrict__ out) {
    int w = (blockIdx.x * blockDim.x + threadIdx.x) >> 5;
    int lane = threadIdx.x & 31;
    if (w >= N_NODES) return;

    int slot = lane >> 3;   // which of 4 concurrent edges
    int sub  = lane & 7;    // which 16B chunk of the 128B row

    int s = __ldg(&row_start[w]);
    int e = __ldg(&row_start[w + 1]);

    const char* gbase = (const char*)g + sub * 16;   // lane's chunk base

    unsigned long long acc0 = 0ull, acc1 = 0ull, acc2 = 0ull, acc3 = 0ull;

    int i = s;
    int   ca = 0, cb = 0;
    float va = 0.f, vb = 0.f;
    if (i + 8 <= e) {
        ca = __ldcs(&edge_col[i + slot]);
        va = __ldcs(&edge_val[i + slot]);
        cb = __ldcs(&edge_col[i + 4 + slot]);
        vb = __ldcs(&edge_val[i + 4 + slot]);
    }
    while (i + 8 <= e) {
        int ni = i + 8;
        int   nca = 0, ncb = 0;
        float nva = 0.f, nvb = 0.f;
        if (ni + 8 <= e) {                       // prefetch next iteration
            nca = __ldcs(&edge_col[ni + slot]);
            nva = __ldcs(&edge_val[ni + slot]);
            ncb = __ldcs(&edge_col[ni + 4 + slot]);
            nvb = __ldcs(&edge_val[ni + 4 + slot]);
        }
        uint4 A = *(const uint4*)(gbase + (size_t)ca * 128);
        uint4 B = *(const uint4*)(gbase + (size_t)cb * 128);
        unsigned long long vva = packff(va, va);
        unsigned long long vvb = packff(vb, vb);
        acc0 = fma2(h2_to_f32x2(A.x), vva, acc0);
        acc1 = fma2(h2_to_f32x2(A.y), vva, acc1);
        acc2 = fma2(h2_to_f32x2(A.z), vva, acc2);
        acc3 = fma2(h2_to_f32x2(A.w), vva, acc3);
        acc0 = fma2(h2_to_f32x2(B.x), vvb, acc0);
        acc1 = fma2(h2_to_f32x2(B.y), vvb, acc1);
        acc2 = fma2(h2_to_f32x2(B.z), vvb, acc2);
        acc3 = fma2(h2_to_f32x2(B.w), vvb, acc3);
        ca = nca; va = nva; cb = ncb; vb = nvb;
        i = ni;
    }
    // tail: 4 edges per step, invalid slots contribute v=0
    for (; i < e; i += 4) {
        int  m = i + slot;
        bool p = (m < e);
        int  mm = p ? m : i;
        int   c = __ldcs(&edge_col[mm]);
        float v = p ? __ldcs(&edge_val[mm]) : 0.f;
        uint4 A = *(const uint4*)(gbase + (size_t)c * 128);
        unsigned long long vv = packff(v, v);
        acc0 = fma2(h2_to_f32x2(A.x), vv, acc0);
        acc1 = fma2(h2_to_f32x2(A.y), vv, acc1);
        acc2 = fma2(h2_to_f32x2(A.z), vv, acc2);
        acc3 = fma2(h2_to_f32x2(A.w), vv, acc3);
    }

    float r0, r1, r2, r3, r4, r5, r6, r7;
    unpack2(acc0, r0, r1);
    unpack2(acc1, r2, r3);
    unpack2(acc2, r4, r5);
    unpack2(acc3, r6, r7);

    // reduce the 4 slots (feature chunks identical by sub)
    r0 += __shfl_xor_sync(0xffffffffu, r0, 8);
    r1 += __shfl_xor_sync(0xffffffffu, r1, 8);
    r2 += __shfl_xor_sync(0xffffffffu, r2, 8);
    r3 += __shfl_xor_sync(0xffffffffu, r3, 8);
    r4 += __shfl_xor_sync(0xffffffffu, r4, 8);
    r5 += __shfl_xor_sync(0xffffffffu, r5, 8);
    r6 += __shfl_xor_sync(0xffffffffu, r6, 8);
    r7 += __shfl_xor_sync(0xffffffffu, r7, 8);
    r0 += __shfl_xor_sync(0xffffffffu, r0, 16);
    r1 += __shfl_xor_sync(0xffffffffu, r1, 16);
    r2 += __shfl_xor_sync(0xffffffffu, r2, 16);
    r3 += __shfl_xor_sync(0xffffffffu, r3, 16);
    r4 += __shfl_xor_sync(0xffffffffu, r4, 16);
    r5 += __shfl_xor_sync(0xffffffffu, r5, 16);
    r6 += __shfl_xor_sync(0xffffffffu, r6, 16);
    r7 += __shfl_xor_sync(0xffffffffu, r7, 16);

    if (lane < 8) {
        float4 b0 = ((const float4*)b)[lane * 2];
        float4 b1 = ((const float4*)b)[lane * 2 + 1];
        float4 o0 = make_float4(r0 + b0.x, r1 + b0.y, r2 + b0.z, r3 + b0.w);
        float4 o1 = make_float4(r4 + b1.x, r5 + b1.y, r6 + b1.z, r7 + b1.w);
        float4* op = (float4*)(out + (size_t)w * 64 + lane * 8);
        __stcs(&op[0], o0);
        __stcs(&op[1], o1);
    }
}

// ---------------------------------------------------------------------------
extern "C" void kernel_launch(void* const* d_in, const int* in_sizes, int n_in,
                              void* d_out, int out_size) {
    const float* feat     = (const float*)d_in[0];
    const int*   edge_row = (const int*)  d_in[1];
    const int*   edge_col = (const int*)  d_in[2];
    const float* edge_val = (const float*)d_in[3];
    const float* W        = (const float*)d_in[4];
    const float* b        = (const float*)d_in[5];
    float*       out      = (float*)d_out;

    __half* g;
    int*    row_start;
    cudaGetSymbolAddress((void**)&g, g_buf);
    cudaGetSymbolAddress((void**)&row_start, g_row_start);

    // 1) fused: rowptr scan + g = half(feat @ W^T)
    prep_kernel<<<NB_ROW + NB_GEMM, 256>>>(edge_row, row_start, feat, W, g);

    // 2) out = A @ g + b   (one warp per node, pipelined 8-lane gathers)
    int total_threads = N_NODES * 32;
    spmm_kernel<<<(total_threads + 255) / 256, 256>>>(row_start, edge_col, edge_val,
                                                      g, b, out);
}